// round 1
// baseline (speedup 1.0000x reference)
#include <cuda_runtime.h>

// Problem constants
#define SQ 2048
#define DM 1024
#define NH 8

// Scratch (device globals; no allocation allowed)
__device__ float g_hidden[(long)SQ * DM];            // 8 MB
__device__ float g_rel[(long)SQ * DM];               // 8 MB
__device__ float g_scores[(long)NH * SQ * DM];       // 64 MB  raw [H,S,D]
__device__ float g_logits[(long)NH * SQ * SQ];       // 128 MB [H,S,S], softmaxed in place
__device__ float g_context[(long)SQ * NH * DM];      // 64 MB  [S, H*D]

// ---------------------------------------------------------------------------
// Kernel 1: hidden = relu(relations @ re_w1 + b1)   (K=4, elementwise-ish)
// ---------------------------------------------------------------------------
__global__ void rel_hidden_kernel(const float* __restrict__ relations,
                                  const float* __restrict__ w1,
                                  const float* __restrict__ b1,
                                  float* __restrict__ hidden)
{
    int idx = blockIdx.x * blockDim.x + threadIdx.x;   // over S*D
    int s = idx >> 10;        // / DM
    int d = idx & (DM - 1);   // % DM
    float r0 = relations[s * 4 + 0];
    float r1 = relations[s * 4 + 1];
    float r2 = relations[s * 4 + 2];
    float r3 = relations[s * 4 + 3];
    float v = b1[d];
    v = fmaf(r0, w1[0 * DM + d], v);
    v = fmaf(r1, w1[1 * DM + d], v);
    v = fmaf(r2, w1[2 * DM + d], v);
    v = fmaf(r3, w1[3 * DM + d], v);
    hidden[idx] = fmaxf(v, 0.0f);
}

// ---------------------------------------------------------------------------
// Tiled SGEMM: C = A @ B (+bias), optionally B transposed (B is [N,K] row-major)
// BM=BN=128, BK=16, 256 threads, 8x8 per-thread tile.
// All dims are multiples of tile sizes for this problem -> no bounds checks.
// Batched via blockIdx.z with element strides.
// ---------------------------------------------------------------------------
template <bool TRANS_B>
__global__ __launch_bounds__(256)
void gemm_kernel(const float* __restrict__ A,
                 const float* __restrict__ B,
                 float* __restrict__ C,
                 const float* __restrict__ bias,
                 int M, int N, int K,
                 int lda, int ldb, int ldc,
                 long long strideAb, long long strideBb, long long strideCb)
{
    constexpr int BM = 128, BN = 128, BK = 16, TM = 8, TN = 8;
    __shared__ float As[BK][BM];
    __shared__ float Bs[BK][BN + 4];

    const int bz = blockIdx.z;
    A += (long long)bz * strideAb;
    B += (long long)bz * strideBb;
    C += (long long)bz * strideCb;

    const int bm = blockIdx.y * BM;
    const int bn = blockIdx.x * BN;

    const int tid = threadIdx.x;      // 0..255
    const int tx = tid & 15;          // 0..15
    const int ty = tid >> 4;          // 0..15

    float acc[TM][TN] = {};
    float a_frag[TM], b_frag[TN];

    for (int k0 = 0; k0 < K; k0 += BK) {
        // Load A tile (128 x 16), float4 along K, transpose into As[k][m]
        {
            int t = tid;
#pragma unroll
            for (int r = 0; r < 2; r++, t += 256) {
                int row = t >> 2;            // 0..127
                int c4  = (t & 3) << 2;      // 0,4,8,12
                float4 v = *(const float4*)&A[(long long)(bm + row) * lda + k0 + c4];
                As[c4 + 0][row] = v.x;
                As[c4 + 1][row] = v.y;
                As[c4 + 2][row] = v.z;
                As[c4 + 3][row] = v.w;
            }
        }
        if (!TRANS_B) {
            // B [K,N]: tile 16 x 128, direct
            int t = tid;
#pragma unroll
            for (int r = 0; r < 2; r++, t += 256) {
                int row = t >> 5;            // 0..15
                int c4  = (t & 31) << 2;     // 0..124
                float4 v = *(const float4*)&B[(long long)(k0 + row) * ldb + bn + c4];
                *(float4*)&Bs[row][c4] = v;
            }
        } else {
            // B [N,K] row-major: tile 128(n) x 16(k), transpose into Bs[k][n]
            int t = tid;
#pragma unroll
            for (int r = 0; r < 2; r++, t += 256) {
                int row = t >> 2;            // 0..127 (n within tile)
                int c4  = (t & 3) << 2;      // 0,4,8,12 (k within tile)
                float4 v = *(const float4*)&B[(long long)(bn + row) * ldb + k0 + c4];
                Bs[c4 + 0][row] = v.x;
                Bs[c4 + 1][row] = v.y;
                Bs[c4 + 2][row] = v.z;
                Bs[c4 + 3][row] = v.w;
            }
        }
        __syncthreads();

#pragma unroll
        for (int k = 0; k < BK; k++) {
#pragma unroll
            for (int i = 0; i < TM; i++) a_frag[i] = As[k][ty * TM + i];
#pragma unroll
            for (int j = 0; j < TN; j++) b_frag[j] = Bs[k][tx * TN + j];
#pragma unroll
            for (int i = 0; i < TM; i++)
#pragma unroll
                for (int j = 0; j < TN; j++)
                    acc[i][j] = fmaf(a_frag[i], b_frag[j], acc[i][j]);
        }
        __syncthreads();
    }

    // Epilogue
#pragma unroll
    for (int i = 0; i < TM; i++) {
        int row = bm + ty * TM + i;
#pragma unroll
        for (int j = 0; j < TN; j += 4) {
            int col = bn + tx * TN + j;
            float4 v = make_float4(acc[i][j], acc[i][j + 1], acc[i][j + 2], acc[i][j + 3]);
            if (bias) {
                v.x += bias[col + 0];
                v.y += bias[col + 1];
                v.z += bias[col + 2];
                v.w += bias[col + 3];
            }
            *(float4*)&C[(long long)row * ldc + col] = v;
        }
    }
}

// ---------------------------------------------------------------------------
// Softmax over rows of length S (in place). One block per row.
// ---------------------------------------------------------------------------
__global__ void softmax_kernel(float* __restrict__ logits)
{
    float* row = logits + (long long)blockIdx.x * SQ;
    __shared__ float red[256];
    int t = threadIdx.x;

    float m = -3.4e38f;
    for (int i = t; i < SQ; i += 256) m = fmaxf(m, row[i]);
    red[t] = m;
    __syncthreads();
    for (int s = 128; s > 0; s >>= 1) {
        if (t < s) red[t] = fmaxf(red[t], red[t + s]);
        __syncthreads();
    }
    m = red[0];
    __syncthreads();

    float sum = 0.0f;
    for (int i = t; i < SQ; i += 256) {
        float e = __expf(row[i] - m);
        row[i] = e;
        sum += e;
    }
    red[t] = sum;
    __syncthreads();
    for (int s = 128; s > 0; s >>= 1) {
        if (t < s) red[t] += red[t + s];
        __syncthreads();
    }
    float inv = 1.0f / red[0];
    for (int i = t; i < SQ; i += 256) row[i] *= inv;
}

// ---------------------------------------------------------------------------
// Launch
// Inputs: 0:x [S,D]  1:relations [S,4]  2:re_w1 [4,D]  3:re_b1 [D]
//         4:re_w2 [D,D]  5:re_b2 [D]  6:attn_w [H,D,D]  7:out_w [H*D,D]  8:out_b [D]
// Output: [S,D] float
// ---------------------------------------------------------------------------
extern "C" void kernel_launch(void* const* d_in, const int* in_sizes, int n_in,
                              void* d_out, int out_size)
{
    const float* x         = (const float*)d_in[0];
    const float* relations = (const float*)d_in[1];
    const float* re_w1     = (const float*)d_in[2];
    const float* re_b1     = (const float*)d_in[3];
    const float* re_w2     = (const float*)d_in[4];
    const float* re_b2     = (const float*)d_in[5];
    const float* attn_w    = (const float*)d_in[6];
    const float* out_w     = (const float*)d_in[7];
    const float* out_b     = (const float*)d_in[8];
    float* out = (float*)d_out;

    float *hidden, *rel, *scores, *logits, *context;
    cudaGetSymbolAddress((void**)&hidden,  g_hidden);
    cudaGetSymbolAddress((void**)&rel,     g_rel);
    cudaGetSymbolAddress((void**)&scores,  g_scores);
    cudaGetSymbolAddress((void**)&logits,  g_logits);
    cudaGetSymbolAddress((void**)&context, g_context);

    // 1) hidden = relu(relations @ re_w1 + b1)
    rel_hidden_kernel<<<(SQ * DM) / 256, 256>>>(relations, re_w1, re_b1, hidden);

    // 2) rel = hidden @ re_w2 + b2          [2048,1024] = [2048,1024]@[1024,1024]
    gemm_kernel<false><<<dim3(DM / 128, SQ / 128, 1), 256>>>(
        hidden, re_w2, rel, re_b2,
        SQ, DM, DM, DM, DM, DM, 0, 0, 0);

    // 3) scores[h] = x @ attn_w[h]          8 x [2048,1024]@[1024,1024]
    gemm_kernel<false><<<dim3(DM / 128, SQ / 128, NH), 256>>>(
        x, attn_w, scores, nullptr,
        SQ, DM, DM, DM, DM, DM,
        0, (long long)DM * DM, (long long)SQ * DM);

    // 4) logits[h] = rel @ K_h^T            K_h row t = scores + (t*H + h)*D (contiguous)
    gemm_kernel<true><<<dim3(SQ / 128, SQ / 128, NH), 256>>>(
        rel, scores, logits, nullptr,
        SQ, SQ, DM, DM, NH * DM, SQ,
        0, (long long)DM, (long long)SQ * SQ);

    // 5) softmax rows (in place)
    softmax_kernel<<<NH * SQ, 256>>>(logits);

    // 6) context[s, h*D + d] = sum_t A[h,s,t] * x[t,d]
    gemm_kernel<false><<<dim3(DM / 128, SQ / 128, NH), 256>>>(
        logits, x, context, nullptr,
        SQ, DM, SQ, SQ, DM, NH * DM,
        (long long)SQ * SQ, 0, (long long)DM);

    // 7) out = context @ out_w + out_b      [2048,8192]@[8192,1024]
    gemm_kernel<false><<<dim3(DM / 128, SQ / 128, 1), 256>>>(
        context, out_w, out, out_b,
        SQ, DM, NH * DM, NH * DM, DM, DM, 0, 0, 0);

    (void)in_sizes; (void)n_in; (void)out_size;
}

// round 5
// speedup vs baseline: 1.4803x; 1.4803x over previous
#include <cuda_runtime.h>
#include <cstdint>

#define SQ 2048
#define DM 1024
#define NH 8

// Scratch (device globals; no allocation allowed)
__device__ float g_hidden[(long)SQ * DM];            // 8 MB
__device__ float g_rel[(long)SQ * DM];               // 8 MB
__device__ float g_scores[(long)NH * SQ * DM];       // 64 MB  raw [H,S,D]
__device__ float g_logits[(long)NH * SQ * SQ];       // 128 MB [H,S,S]
__device__ float g_context[(long)SQ * NH * DM];      // 64 MB  [S, H*D]

// ---------------------------------------------------------------------------
// helpers
// ---------------------------------------------------------------------------
__device__ __forceinline__ uint32_t f2tf32(float x) {
    uint32_t y;
    asm("cvt.rna.tf32.f32 %0, %1;" : "=r"(y) : "f"(x));
    return y;
}

__device__ __forceinline__ void cp_async16(uint32_t smem_dst, const void* gmem_src) {
    asm volatile("cp.async.cg.shared.global [%0], [%1], 16;\n" ::
                 "r"(smem_dst), "l"(gmem_src));
}
__device__ __forceinline__ void cp_commit() {
    asm volatile("cp.async.commit_group;\n" ::: "memory");
}
template <int N>
__device__ __forceinline__ void cp_wait() {
    asm volatile("cp.async.wait_group %0;\n" :: "n"(N) : "memory");
}

__device__ __forceinline__ void mma_tf32(float c[4], const uint32_t a[4], const uint32_t b[2]) {
    asm volatile(
        "mma.sync.aligned.m16n8k8.row.col.f32.tf32.tf32.f32 "
        "{%0,%1,%2,%3}, {%4,%5,%6,%7}, {%8,%9}, {%0,%1,%2,%3};\n"
        : "+f"(c[0]), "+f"(c[1]), "+f"(c[2]), "+f"(c[3])
        : "r"(a[0]), "r"(a[1]), "r"(a[2]), "r"(a[3]), "r"(b[0]), "r"(b[1]));
}

// ---------------------------------------------------------------------------
// Kernel 1: hidden = relu(relations @ re_w1 + b1)
// ---------------------------------------------------------------------------
__global__ void rel_hidden_kernel(const float* __restrict__ relations,
                                  const float* __restrict__ w1,
                                  const float* __restrict__ b1,
                                  float* __restrict__ hidden)
{
    int idx = blockIdx.x * blockDim.x + threadIdx.x;
    int s = idx >> 10;
    int d = idx & (DM - 1);
    float r0 = relations[s * 4 + 0];
    float r1 = relations[s * 4 + 1];
    float r2 = relations[s * 4 + 2];
    float r3 = relations[s * 4 + 3];
    float v = b1[d];
    v = fmaf(r0, w1[0 * DM + d], v);
    v = fmaf(r1, w1[1 * DM + d], v);
    v = fmaf(r2, w1[2 * DM + d], v);
    v = fmaf(r3, w1[3 * DM + d], v);
    hidden[idx] = fmaxf(v, 0.0f);
}

// ---------------------------------------------------------------------------
// 3xTF32 tensor-core GEMM (error-compensated, ~fp32 accuracy).
// CTA tile 128x128, BK=32, 256 threads (8 warps, each 64x32 via 4x4 grid of
// m16n8k8 mma). cp.async double buffering.
//   TRANS_B=false: B is [K,N] row-major.   smem Bs[32][136]
//   TRANS_B=true : B is [N,K] row-major.   smem Bs[128][36]
//   As always [128][36] from A [M,K] row-major.
// Each fp32 operand is split hi/lo in tf32; 3 MMAs: hi*hi + hi*lo + lo*hi.
// ---------------------------------------------------------------------------
#define A_STAGE (128 * 36)
#define BN_STAGE (32 * 136)
#define BT_STAGE (128 * 36)

template <bool TRANS_B>
__global__ __launch_bounds__(256, 1)
void gemm_tf32x3(const float* __restrict__ A,
                 const float* __restrict__ B,
                 float* __restrict__ C,
                 const float* __restrict__ bias,
                 int K, int lda, int ldb, int ldc,
                 long long strideAb, long long strideBb, long long strideCb)
{
    extern __shared__ float smem[];
    constexpr int B_STAGE = TRANS_B ? BT_STAGE : BN_STAGE;
    float* As = smem;                 // [2][128][36]
    float* Bs = smem + 2 * A_STAGE;   // [2][B_STAGE]

    const int bz = blockIdx.z;
    A += (long long)bz * strideAb;
    B += (long long)bz * strideBb;
    C += (long long)bz * strideCb;

    const int bm = blockIdx.y * 128;
    const int bn = blockIdx.x * 128;

    const int tid  = threadIdx.x;
    const int w    = tid >> 5;
    const int lane = tid & 31;
    const int q    = lane >> 2;   // groupID
    const int r    = lane & 3;    // threadID in group
    const int wm   = (w & 1) * 64;
    const int wn   = (w >> 1) * 32;

    // ---- stage loaders -----------------------------------------------------
    auto load_stage = [&](int stage, int k0) {
        {
            float* dstA = As + stage * A_STAGE;
#pragma unroll
            for (int i = 0; i < 4; i++) {
                int c   = tid + 256 * i;
                int row = c >> 3;
                int j   = (c & 7) << 2;
                uint32_t d = (uint32_t)__cvta_generic_to_shared(&dstA[row * 36 + j]);
                cp_async16(d, &A[(long long)(bm + row) * lda + k0 + j]);
            }
        }
        if (!TRANS_B) {
            float* dstB = Bs + stage * B_STAGE;
#pragma unroll
            for (int i = 0; i < 4; i++) {
                int c   = tid + 256 * i;
                int row = c >> 5;
                int j   = (c & 31) << 2;
                uint32_t d = (uint32_t)__cvta_generic_to_shared(&dstB[row * 136 + j]);
                cp_async16(d, &B[(long long)(k0 + row) * ldb + bn + j]);
            }
        } else {
            float* dstB = Bs + stage * B_STAGE;
#pragma unroll
            for (int i = 0; i < 4; i++) {
                int c   = tid + 256 * i;
                int row = c >> 3;
                int j   = (c & 7) << 2;
                uint32_t d = (uint32_t)__cvta_generic_to_shared(&dstB[row * 36 + j]);
                cp_async16(d, &B[(long long)(bn + row) * ldb + k0 + j]);
            }
        }
    };

    float acc[4][4][4] = {};

    const int iters = K >> 5;   // K / 32
    load_stage(0, 0);
    cp_commit();

    for (int it = 0; it < iters; ++it) {
        if (it + 1 < iters) {
            load_stage((it + 1) & 1, (it + 1) << 5);
            cp_commit();
            cp_wait<1>();
        } else {
            cp_wait<0>();
        }
        __syncthreads();

        const float* as = As + (it & 1) * A_STAGE;
        const float* bs = Bs + (it & 1) * B_STAGE;

#pragma unroll
        for (int kk = 0; kk < 32; kk += 8) {
            uint32_t ah[4][4], al[4][4];
#pragma unroll
            for (int mi = 0; mi < 4; mi++) {
                int m0 = wm + mi * 16 + q;
                float v0 = as[(m0)     * 36 + kk + r];
                float v1 = as[(m0 + 8) * 36 + kk + r];
                float v2 = as[(m0)     * 36 + kk + r + 4];
                float v3 = as[(m0 + 8) * 36 + kk + r + 4];
                ah[mi][0] = f2tf32(v0); al[mi][0] = f2tf32(v0 - __uint_as_float(ah[mi][0]));
                ah[mi][1] = f2tf32(v1); al[mi][1] = f2tf32(v1 - __uint_as_float(ah[mi][1]));
                ah[mi][2] = f2tf32(v2); al[mi][2] = f2tf32(v2 - __uint_as_float(ah[mi][2]));
                ah[mi][3] = f2tf32(v3); al[mi][3] = f2tf32(v3 - __uint_as_float(ah[mi][3]));
            }
            uint32_t bh[4][2], bl[4][2];
#pragma unroll
            for (int ni = 0; ni < 4; ni++) {
                int n0 = wn + ni * 8 + q;
                float u0, u1;
                if (TRANS_B) {
                    u0 = bs[n0 * 36 + kk + r];
                    u1 = bs[n0 * 36 + kk + r + 4];
                } else {
                    u0 = bs[(kk + r)     * 136 + n0];
                    u1 = bs[(kk + r + 4) * 136 + n0];
                }
                bh[ni][0] = f2tf32(u0); bl[ni][0] = f2tf32(u0 - __uint_as_float(bh[ni][0]));
                bh[ni][1] = f2tf32(u1); bl[ni][1] = f2tf32(u1 - __uint_as_float(bh[ni][1]));
            }
#pragma unroll
            for (int mi = 0; mi < 4; mi++)
#pragma unroll
                for (int ni = 0; ni < 4; ni++) {
                    mma_tf32(acc[mi][ni], ah[mi], bl[ni]);
                    mma_tf32(acc[mi][ni], al[mi], bh[ni]);
                    mma_tf32(acc[mi][ni], ah[mi], bh[ni]);
                }
        }
        __syncthreads();
    }

    // ---- epilogue ----------------------------------------------------------
#pragma unroll
    for (int mi = 0; mi < 4; mi++) {
#pragma unroll
        for (int ni = 0; ni < 4; ni++) {
            int row = bm + wm + mi * 16 + q;
            int col = bn + wn + ni * 8 + 2 * r;
            float2 v0 = make_float2(acc[mi][ni][0], acc[mi][ni][1]);
            float2 v1 = make_float2(acc[mi][ni][2], acc[mi][ni][3]);
            if (bias) {
                float2 bb = *(const float2*)&bias[col];
                v0.x += bb.x; v0.y += bb.y;
                v1.x += bb.x; v1.y += bb.y;
            }
            *(float2*)&C[(long long)row * ldc + col]       = v0;
            *(float2*)&C[(long long)(row + 8) * ldc + col] = v1;
        }
    }
}

// ---------------------------------------------------------------------------
// Softmax over rows of length S (in place). One block per row.
// ---------------------------------------------------------------------------
__global__ void softmax_kernel(float* __restrict__ logits)
{
    float* row = logits + (long long)blockIdx.x * SQ;
    __shared__ float red[256];
    int t = threadIdx.x;

    float m = -3.4e38f;
    for (int i = t; i < SQ; i += 256) m = fmaxf(m, row[i]);
    red[t] = m;
    __syncthreads();
    for (int s = 128; s > 0; s >>= 1) {
        if (t < s) red[t] = fmaxf(red[t], red[t + s]);
        __syncthreads();
    }
    m = red[0];
    __syncthreads();

    float sum = 0.0f;
    for (int i = t; i < SQ; i += 256) {
        float e = __expf(row[i] - m);
        row[i] = e;
        sum += e;
    }
    red[t] = sum;
    __syncthreads();
    for (int s = 128; s > 0; s >>= 1) {
        if (t < s) red[t] += red[t + s];
        __syncthreads();
    }
    float inv = 1.0f / red[0];
    for (int i = t; i < SQ; i += 256) row[i] *= inv;
}

// ---------------------------------------------------------------------------
// Launch
// ---------------------------------------------------------------------------
extern "C" void kernel_launch(void* const* d_in, const int* in_sizes, int n_in,
                              void* d_out, int out_size)
{
    const float* x         = (const float*)d_in[0];
    const float* relations = (const float*)d_in[1];
    const float* re_w1     = (const float*)d_in[2];
    const float* re_b1     = (const float*)d_in[3];
    const float* re_w2     = (const float*)d_in[4];
    const float* re_b2     = (const float*)d_in[5];
    const float* attn_w    = (const float*)d_in[6];
    const float* out_w     = (const float*)d_in[7];
    const float* out_b     = (const float*)d_in[8];
    float* out = (float*)d_out;

    float *hidden, *rel, *scores, *logits, *context;
    cudaGetSymbolAddress((void**)&hidden,  g_hidden);
    cudaGetSymbolAddress((void**)&rel,     g_rel);
    cudaGetSymbolAddress((void**)&scores,  g_scores);
    cudaGetSymbolAddress((void**)&logits,  g_logits);
    cudaGetSymbolAddress((void**)&context, g_context);

    const int smemN = (2 * A_STAGE + 2 * BN_STAGE) * 4;   // 71680
    const int smemT = (2 * A_STAGE + 2 * BT_STAGE) * 4;   // 73728
    static bool attr_done = false;
    if (!attr_done) {
        cudaFuncSetAttribute(gemm_tf32x3<false>, cudaFuncAttributeMaxDynamicSharedMemorySize, smemN);
        cudaFuncSetAttribute(gemm_tf32x3<true>,  cudaFuncAttributeMaxDynamicSharedMemorySize, smemT);
        attr_done = true;
    }

    // 1) hidden = relu(relations @ re_w1 + b1)
    rel_hidden_kernel<<<(SQ * DM) / 256, 256>>>(relations, re_w1, re_b1, hidden);

    // 2) rel = hidden @ re_w2 + b2
    gemm_tf32x3<false><<<dim3(DM / 128, SQ / 128, 1), 256, smemN>>>(
        hidden, re_w2, rel, re_b2, DM, DM, DM, DM, 0, 0, 0);

    // 3) scores[h] = x @ attn_w[h]
    gemm_tf32x3<false><<<dim3(DM / 128, SQ / 128, NH), 256, smemN>>>(
        x, attn_w, scores, nullptr, DM, DM, DM, DM,
        0, (long long)DM * DM, (long long)SQ * DM);

    // 4) logits[h] = rel @ K_h^T ; K_h row t = scores + (t*H + h)*D (contiguous)
    gemm_tf32x3<true><<<dim3(SQ / 128, SQ / 128, NH), 256, smemT>>>(
        rel, scores, logits, nullptr, DM, DM, NH * DM, SQ,
        0, (long long)DM, (long long)SQ * SQ);

    // 5) softmax rows (in place)
    softmax_kernel<<<NH * SQ, 256>>>(logits);

    // 6) context[s, h*D + d] = sum_t A[h,s,t] * x[t,d]
    gemm_tf32x3<false><<<dim3(DM / 128, SQ / 128, NH), 256, smemN>>>(
        logits, x, context, nullptr, SQ, SQ, DM, NH * DM,
        (long long)SQ * SQ, 0, (long long)DM);

    // 7) out = context @ out_w + out_b
    gemm_tf32x3<false><<<dim3(DM / 128, SQ / 128, 1), 256, smemN>>>(
        context, out_w, out, out_b, NH * DM, NH * DM, DM, DM, 0, 0, 0);

    (void)in_sizes; (void)n_in; (void)out_size;
}

// round 7
// speedup vs baseline: 1.5414x; 1.0413x over previous
#include <cuda_runtime.h>
#include <cstdint>

#define SQ 2048
#define DM 1024
#define NH 8

// ---------------------------------------------------------------------------
// Scratch (device globals; no allocation allowed)
// ---------------------------------------------------------------------------
__device__ float g_hidden[(long)SQ * DM];            // 8 MB
__device__ float g_rel[(long)SQ * DM];               // 8 MB
__device__ float g_scores[(long)NH * SQ * DM];       // 64 MB  raw [H,S,D]
__device__ float g_logits[(long)NH * SQ * SQ];       // 128 MB [H,S,S]
__device__ float g_context[(long)SQ * NH * DM];      // 64 MB  [S, H*D]
__device__ float g_rew2T[(long)DM * DM];             // 4 MB   re_w2^T   [N,K]
__device__ float g_attnwT[(long)NH * DM * DM];       // 32 MB  attn_w^T per head
__device__ float g_outwT[(long)DM * NH * DM];        // 32 MB  out_w^T   [1024, 8192]
__device__ float g_xT[(long)DM * SQ];                // 8 MB   x^T       [1024, 2048]

// ---------------------------------------------------------------------------
// helpers
// ---------------------------------------------------------------------------
__device__ __forceinline__ uint32_t f2tf32(float x) {
    uint32_t y;
    asm("cvt.rna.tf32.f32 %0, %1;" : "=r"(y) : "f"(x));
    return y;
}

__device__ __forceinline__ void mma_tf32(float c[4], const uint32_t a[4], const uint32_t b[2]) {
    asm volatile(
        "mma.sync.aligned.m16n8k8.row.col.f32.tf32.tf32.f32 "
        "{%0,%1,%2,%3}, {%4,%5,%6,%7}, {%8,%9}, {%0,%1,%2,%3};\n"
        : "+f"(c[0]), "+f"(c[1]), "+f"(c[2]), "+f"(c[3])
        : "r"(a[0]), "r"(a[1]), "r"(a[2]), "r"(a[3]), "r"(b[0]), "r"(b[1]));
}

__device__ __forceinline__ void split4(const float4 v, float4& h, float4& l) {
    h.x = __uint_as_float(f2tf32(v.x)); l.x = __uint_as_float(f2tf32(v.x - h.x));
    h.y = __uint_as_float(f2tf32(v.y)); l.y = __uint_as_float(f2tf32(v.y - h.y));
    h.z = __uint_as_float(f2tf32(v.z)); l.z = __uint_as_float(f2tf32(v.z - h.z));
    h.w = __uint_as_float(f2tf32(v.w)); l.w = __uint_as_float(f2tf32(v.w - h.w));
}

// ---------------------------------------------------------------------------
// hidden = relu(relations @ re_w1 + b1)
// ---------------------------------------------------------------------------
__global__ void rel_hidden_kernel(const float* __restrict__ relations,
                                  const float* __restrict__ w1,
                                  const float* __restrict__ b1,
                                  float* __restrict__ hidden)
{
    int idx = blockIdx.x * blockDim.x + threadIdx.x;
    int s = idx >> 10;
    int d = idx & (DM - 1);
    float v = b1[d];
    v = fmaf(relations[s * 4 + 0], w1[0 * DM + d], v);
    v = fmaf(relations[s * 4 + 1], w1[1 * DM + d], v);
    v = fmaf(relations[s * 4 + 2], w1[2 * DM + d], v);
    v = fmaf(relations[s * 4 + 3], w1[3 * DM + d], v);
    hidden[idx] = fmaxf(v, 0.0f);
}

// ---------------------------------------------------------------------------
// Transpose: out[b][c][r] = in[b][r][c]. R, C multiples of 32. block (32,8).
// ---------------------------------------------------------------------------
__global__ void transpose_kernel(const float* __restrict__ in, float* __restrict__ out,
                                 int R, int C, long long strideIn, long long strideOut)
{
    __shared__ float t[32][33];
    in  += (long long)blockIdx.z * strideIn;
    out += (long long)blockIdx.z * strideOut;
    int r0 = blockIdx.y * 32, c0 = blockIdx.x * 32;
    int tx = threadIdx.x, ty = threadIdx.y;
#pragma unroll
    for (int i = 0; i < 4; i++)
        t[ty + 8 * i][tx] = in[(long long)(r0 + ty + 8 * i) * C + c0 + tx];
    __syncthreads();
#pragma unroll
    for (int i = 0; i < 4; i++)
        out[(long long)(c0 + ty + 8 * i) * R + r0 + tx] = t[tx][ty + 8 * i];
}

// ---------------------------------------------------------------------------
// 3xTF32 NT GEMM with pre-split smem tiles.
//   C[M,N] = A[M,K] @ B[N,K]^T (+bias)
// CTA tile 128x128, BK=32, 256 threads (8 warps, each 64x32 of m16n8k8).
// smem per stage: Ah, Al, Bh, Bl tiles, each [128 rows][36 floats] (stride pad).
// Split (cvt.rna hi / residual lo) done once at the STS stage; inner loop is
// pure LDS.32 (conflict-free) + MMA, term-major for accumulator independence.
// Double-buffered; LDG for stage s+2 issued after STS of s+1.
// ---------------------------------------------------------------------------
#define TILE_F 4608            // 128 * 36 floats
#define STAGE_F (4 * TILE_F)   // Ah Al Bh Bl

__global__ __launch_bounds__(256)
void gemm_nt_x3(const float* __restrict__ A,
                const float* __restrict__ B,
                float* __restrict__ C,
                const float* __restrict__ bias,
                int K, int lda, int ldb, int ldc,
                long long strideAb, long long strideBb, long long strideCb)
{
    extern __shared__ float sm[];   // [2][4][TILE_F]

    const int tid  = threadIdx.x;
    const int w    = tid >> 5;
    const int lane = tid & 31;
    const int q    = lane >> 2;
    const int r    = lane & 3;
    const int wm   = (w & 1) * 64;
    const int wn   = (w >> 1) * 32;

    A += (long long)blockIdx.z * strideAb;
    B += (long long)blockIdx.z * strideBb;
    C += (long long)blockIdx.z * strideCb;
    const int bm = blockIdx.y * 128;
    const int bn = blockIdx.x * 128;

    float4 stA[4], stB[4];

    auto ldg = [&](int k0) {
#pragma unroll
        for (int i = 0; i < 4; i++) {
            int c = tid + 256 * i;
            int row = c >> 3, kb = (c & 7) << 2;
            stA[i] = *(const float4*)&A[(long long)(bm + row) * lda + k0 + kb];
            stB[i] = *(const float4*)&B[(long long)(bn + row) * ldb + k0 + kb];
        }
    };

    auto sts = [&](int st) {
        float* Ah = sm + st * STAGE_F;
        float* Al = Ah + TILE_F;
        float* Bh = Al + TILE_F;
        float* Bl = Bh + TILE_F;
#pragma unroll
        for (int i = 0; i < 4; i++) {
            int c = tid + 256 * i;
            int row = c >> 3, kb = (c & 7) << 2;
            float4 h, l;
            split4(stA[i], h, l);
            *(float4*)&Ah[row * 36 + kb] = h;
            *(float4*)&Al[row * 36 + kb] = l;
            split4(stB[i], h, l);
            *(float4*)&Bh[row * 36 + kb] = h;
            *(float4*)&Bl[row * 36 + kb] = l;
        }
    };

    float acc[4][4][4] = {};

    auto compute = [&](int st) {
        const uint32_t* Ah = (const uint32_t*)(sm + st * STAGE_F);
        const uint32_t* Al = Ah + TILE_F;
        const uint32_t* Bh = Al + TILE_F;
        const uint32_t* Bl = Bh + TILE_F;
#pragma unroll
        for (int kk = 0; kk < 32; kk += 8) {
            uint32_t ah[4][4], al[4][4], bh[4][2], bl[4][2];
#pragma unroll
            for (int mi = 0; mi < 4; mi++) {
                int m0 = wm + mi * 16 + q;
                ah[mi][0] = Ah[(m0)     * 36 + kk + r];
                ah[mi][1] = Ah[(m0 + 8) * 36 + kk + r];
                ah[mi][2] = Ah[(m0)     * 36 + kk + r + 4];
                ah[mi][3] = Ah[(m0 + 8) * 36 + kk + r + 4];
                al[mi][0] = Al[(m0)     * 36 + kk + r];
                al[mi][1] = Al[(m0 + 8) * 36 + kk + r];
                al[mi][2] = Al[(m0)     * 36 + kk + r + 4];
                al[mi][3] = Al[(m0 + 8) * 36 + kk + r + 4];
            }
#pragma unroll
            for (int ni = 0; ni < 4; ni++) {
                int n0 = wn + ni * 8 + q;
                bh[ni][0] = Bh[n0 * 36 + kk + r];
                bh[ni][1] = Bh[n0 * 36 + kk + r + 4];
                bl[ni][0] = Bl[n0 * 36 + kk + r];
                bl[ni][1] = Bl[n0 * 36 + kk + r + 4];
            }
            // term-major: 16 independent accumulators between reuses
#pragma unroll
            for (int mi = 0; mi < 4; mi++)
#pragma unroll
                for (int ni = 0; ni < 4; ni++)
                    mma_tf32(acc[mi][ni], ah[mi], bl[ni]);
#pragma unroll
            for (int mi = 0; mi < 4; mi++)
#pragma unroll
                for (int ni = 0; ni < 4; ni++)
                    mma_tf32(acc[mi][ni], al[mi], bh[ni]);
#pragma unroll
            for (int mi = 0; mi < 4; mi++)
#pragma unroll
                for (int ni = 0; ni < 4; ni++)
                    mma_tf32(acc[mi][ni], ah[mi], bh[ni]);
        }
    };

    const int iters = K >> 5;

    ldg(0);
    sts(0);
    if (iters > 1) ldg(32);
    __syncthreads();

    for (int it = 0; it < iters; ++it) {
        compute(it & 1);
        if (it + 1 < iters) {
            sts((it + 1) & 1);
            if (it + 2 < iters) ldg((it + 2) << 5);
        }
        __syncthreads();
    }

    // ---- epilogue ----------------------------------------------------------
#pragma unroll
    for (int mi = 0; mi < 4; mi++) {
#pragma unroll
        for (int ni = 0; ni < 4; ni++) {
            int row = bm + wm + mi * 16 + q;
            int col = bn + wn + ni * 8 + 2 * r;
            float2 v0 = make_float2(acc[mi][ni][0], acc[mi][ni][1]);
            float2 v1 = make_float2(acc[mi][ni][2], acc[mi][ni][3]);
            if (bias) {
                float2 bb = *(const float2*)&bias[col];
                v0.x += bb.x; v0.y += bb.y;
                v1.x += bb.x; v1.y += bb.y;
            }
            *(float2*)&C[(long long)row * ldc + col]       = v0;
            *(float2*)&C[(long long)(row + 8) * ldc + col] = v1;
        }
    }
}

// ---------------------------------------------------------------------------
// Softmax over rows of length SQ (in place). One block per row.
// ---------------------------------------------------------------------------
__global__ void softmax_kernel(float* __restrict__ logits)
{
    float* row = logits + (long long)blockIdx.x * SQ;
    __shared__ float red[256];
    int t = threadIdx.x;

    float m = -3.4e38f;
    for (int i = t; i < SQ; i += 256) m = fmaxf(m, row[i]);
    red[t] = m;
    __syncthreads();
    for (int s = 128; s > 0; s >>= 1) {
        if (t < s) red[t] = fmaxf(red[t], red[t + s]);
        __syncthreads();
    }
    m = red[0];
    __syncthreads();

    float sum = 0.0f;
    for (int i = t; i < SQ; i += 256) {
        float e = __expf(row[i] - m);
        row[i] = e;
        sum += e;
    }
    red[t] = sum;
    __syncthreads();
    for (int s = 128; s > 0; s >>= 1) {
        if (t < s) red[t] += red[t + s];
        __syncthreads();
    }
    float inv = 1.0f / red[0];
    for (int i = t; i < SQ; i += 256) row[i] *= inv;
}

// ---------------------------------------------------------------------------
// Launch
// ---------------------------------------------------------------------------
extern "C" void kernel_launch(void* const* d_in, const int* in_sizes, int n_in,
                              void* d_out, int out_size)
{
    const float* x         = (const float*)d_in[0];
    const float* relations = (const float*)d_in[1];
    const float* re_w1     = (const float*)d_in[2];
    const float* re_b1     = (const float*)d_in[3];
    const float* re_w2     = (const float*)d_in[4];
    const float* re_b2     = (const float*)d_in[5];
    const float* attn_w    = (const float*)d_in[6];
    const float* out_w     = (const float*)d_in[7];
    const float* out_b     = (const float*)d_in[8];
    float* out = (float*)d_out;

    float *hidden, *rel, *scores, *logits, *context, *rew2T, *attnwT, *outwT, *xT;
    cudaGetSymbolAddress((void**)&hidden,  g_hidden);
    cudaGetSymbolAddress((void**)&rel,     g_rel);
    cudaGetSymbolAddress((void**)&scores,  g_scores);
    cudaGetSymbolAddress((void**)&logits,  g_logits);
    cudaGetSymbolAddress((void**)&context, g_context);
    cudaGetSymbolAddress((void**)&rew2T,   g_rew2T);
    cudaGetSymbolAddress((void**)&attnwT,  g_attnwT);
    cudaGetSymbolAddress((void**)&outwT,   g_outwT);
    cudaGetSymbolAddress((void**)&xT,      g_xT);

    const int smemB = 2 * STAGE_F * 4;   // 147456 bytes
    cudaFuncSetAttribute(gemm_nt_x3, cudaFuncAttributeMaxDynamicSharedMemorySize, smemB);

    // 0) transposes so every GEMM is NT (B stored [N,K] K-major)
    transpose_kernel<<<dim3(32, 32, 1), dim3(32, 8)>>>(re_w2, rew2T, DM, DM, 0, 0);
    transpose_kernel<<<dim3(32, 32, NH), dim3(32, 8)>>>(attn_w, attnwT, DM, DM,
                                                        (long long)DM * DM, (long long)DM * DM);
    transpose_kernel<<<dim3(32, 256, 1), dim3(32, 8)>>>(out_w, outwT, NH * DM, DM, 0, 0);
    transpose_kernel<<<dim3(32, 64, 1), dim3(32, 8)>>>(x, xT, SQ, DM, 0, 0);

    // 1) hidden = relu(relations @ re_w1 + b1)
    rel_hidden_kernel<<<(SQ * DM) / 256, 256>>>(relations, re_w1, re_b1, hidden);

    // 2) rel = hidden @ re_w2 + b2
    gemm_nt_x3<<<dim3(DM / 128, SQ / 128, 1), 256, smemB>>>(
        hidden, rew2T, rel, re_b2, DM, DM, DM, DM, 0, 0, 0);

    // 3) scores[h] = x @ attn_w[h]
    gemm_nt_x3<<<dim3(DM / 128, SQ / 128, NH), 256, smemB>>>(
        x, attnwT, scores, nullptr, DM, DM, DM, DM,
        0, (long long)DM * DM, (long long)SQ * DM);

    // 4) logits[h] = rel @ K_h^T ; key row t = scores[(t*NH + h)*DM ...] (K-major)
    gemm_nt_x3<<<dim3(SQ / 128, SQ / 128, NH), 256, smemB>>>(
        rel, scores, logits, nullptr, DM, DM, NH * DM, SQ,
        0, (long long)DM, (long long)SQ * SQ);

    // 5) softmax rows (in place)
    softmax_kernel<<<NH * SQ, 256>>>(logits);

    // 6) context[s, h*DM + d] = sum_t attn[h,s,t] * x[t,d]   (B = x^T)
    gemm_nt_x3<<<dim3(DM / 128, SQ / 128, NH), 256, smemB>>>(
        logits, xT, context, nullptr, SQ, SQ, SQ, NH * DM,
        (long long)SQ * SQ, 0, (long long)DM);

    // 7) out = context @ out_w + out_b   (B = out_w^T)
    gemm_nt_x3<<<dim3(DM / 128, SQ / 128, 1), 256, smemB>>>(
        context, outwT, out, out_b, NH * DM, NH * DM, NH * DM, DM, 0, 0, 0);

    (void)in_sizes; (void)n_in; (void)out_size;
}

// round 10
// speedup vs baseline: 2.1612x; 1.4021x over previous
#include <cuda_runtime.h>
#include <cuda_bf16.h>
#include <cstdint>

#define SQ 2048
#define DM 1024
#define NH 8

// ---------------------------------------------------------------------------
// Scratch (device globals; no allocation allowed)
// ---------------------------------------------------------------------------
__device__ float g_hidden[(long)SQ * DM];            // 8 MB
__device__ float g_rel[(long)SQ * DM];               // 8 MB
__device__ float g_scores[(long)NH * SQ * DM];       // 64 MB  raw [H,S,D]
__device__ float g_logits[(long)NH * SQ * SQ];       // 128 MB [H,S,S]
__device__ float g_context[(long)SQ * NH * DM];      // 64 MB  [S, H*D]
__device__ float g_rew2T[(long)DM * DM];             // 4 MB   re_w2^T   [N,K]
__device__ float g_attnwT[(long)NH * DM * DM];       // 32 MB  attn_w^T per head
__device__ float g_outwT[(long)DM * NH * DM];        // 32 MB  out_w^T   [1024, 8192]
__device__ float g_xT[(long)DM * SQ];                // 8 MB   x^T       [1024, 2048]

// ---------------------------------------------------------------------------
// helpers
// ---------------------------------------------------------------------------
__device__ __forceinline__ float f2tf32(float x) {
    uint32_t y;
    asm("cvt.rna.tf32.f32 %0, %1;" : "=r"(y) : "f"(x));
    return __uint_as_float(y);
}
// pack two floats as bf16x2 word {lo in [15:0], hi in [31:16]}
__device__ __forceinline__ uint32_t pack_bf16(float lo, float hi) {
    uint32_t w;
    asm("cvt.rn.bf16x2.f32 %0, %1, %2;" : "=r"(w) : "f"(hi), "f"(lo));
    return w;
}
// unpack bf16x2 word back to the two exact fp32 values it represents
__device__ __forceinline__ void unpack_bf16(uint32_t w, float& lo, float& hi) {
    lo = __uint_as_float(w << 16);
    hi = __uint_as_float(w & 0xFFFF0000u);
}

__device__ __forceinline__ void mma_tf32(float c[4], const uint32_t a[4], const uint32_t b[2]) {
    asm volatile(
        "mma.sync.aligned.m16n8k8.row.col.f32.tf32.tf32.f32 "
        "{%0,%1,%2,%3}, {%4,%5,%6,%7}, {%8,%9}, {%0,%1,%2,%3};\n"
        : "+f"(c[0]), "+f"(c[1]), "+f"(c[2]), "+f"(c[3])
        : "r"(a[0]), "r"(a[1]), "r"(a[2]), "r"(a[3]), "r"(b[0]), "r"(b[1]));
}
__device__ __forceinline__ void mma_bf16(float c[4], const uint32_t a[4], const uint32_t b[2]) {
    asm volatile(
        "mma.sync.aligned.m16n8k16.row.col.f32.bf16.bf16.f32 "
        "{%0,%1,%2,%3}, {%4,%5,%6,%7}, {%8,%9}, {%0,%1,%2,%3};\n"
        : "+f"(c[0]), "+f"(c[1]), "+f"(c[2]), "+f"(c[3])
        : "r"(a[0]), "r"(a[1]), "r"(a[2]), "r"(a[3]), "r"(b[0]), "r"(b[1]));
}

// ---------------------------------------------------------------------------
// hidden = relu(relations @ re_w1 + b1)
// ---------------------------------------------------------------------------
__global__ void rel_hidden_kernel(const float* __restrict__ relations,
                                  const float* __restrict__ w1,
                                  const float* __restrict__ b1,
                                  float* __restrict__ hidden)
{
    int idx = blockIdx.x * blockDim.x + threadIdx.x;
    int s = idx >> 10;
    int d = idx & (DM - 1);
    float v = b1[d];
    v = fmaf(relations[s * 4 + 0], w1[0 * DM + d], v);
    v = fmaf(relations[s * 4 + 1], w1[1 * DM + d], v);
    v = fmaf(relations[s * 4 + 2], w1[2 * DM + d], v);
    v = fmaf(relations[s * 4 + 3], w1[3 * DM + d], v);
    hidden[idx] = fmaxf(v, 0.0f);
}

// ---------------------------------------------------------------------------
// Transpose: out[b][c][r] = in[b][r][c]. R, C multiples of 32. block (32,8).
// ---------------------------------------------------------------------------
__global__ void transpose_kernel(const float* __restrict__ in, float* __restrict__ out,
                                 int R, int C, long long strideIn, long long strideOut)
{
    __shared__ float t[32][33];
    in  += (long long)blockIdx.z * strideIn;
    out += (long long)blockIdx.z * strideOut;
    int r0 = blockIdx.y * 32, c0 = blockIdx.x * 32;
    int tx = threadIdx.x, ty = threadIdx.y;
#pragma unroll
    for (int i = 0; i < 4; i++)
        t[ty + 8 * i][tx] = in[(long long)(r0 + ty + 8 * i) * C + c0 + tx];
    __syncthreads();
#pragma unroll
    for (int i = 0; i < 4; i++)
        out[(long long)(c0 + ty + 8 * i) * R + r0 + tx] = t[tx][ty + 8 * i];
}

// ---------------------------------------------------------------------------
// Shared GEMM skeleton: C[M,N] = A[M,K] @ B[N,K]^T (+bias), NT, CTA 128x128,
// BK=32, 256 threads, warp tile 64x32 (4x4 of m16n8).
//
// HYBRID=1 (pre-softmax chain, ~1e-6/term): per k16:
//    2x tf32 m16n8k8 (Ah*Bh) + 2x bf16 m16n8k16 (bf16(Ah)*Bl + Al*bf16(Bh))
// HYBRID=0 (post-softmax, bf16x2, ~5e-5/term): per k16:
//    3x bf16 m16n8k16 (Ah*Bh + Ah*Bl + Al*Bh), ah=bf16(a), al=bf16(a-ah)
//
// smem tiles per stage:
//   HYBRID: AhF,BhF float [128][36]; AHB,ALB,BHB,BLB bf16x2 [128][20] u32
//   bf16x2: AHB,ALB,BHB,BLB only
// ---------------------------------------------------------------------------
#define TFT_B 18432            // tf32 tile bytes  (128*36*4)
#define BFT_B 10240            // bf16 tile bytes  (128*20*4)
#define STAGE_HYB (2 * TFT_B + 4 * BFT_B)   // 77824
#define STAGE_BF2 (4 * BFT_B)               // 40960

template <int HYBRID>
__global__ __launch_bounds__(256)
void gemm_nt(const float* __restrict__ A,
             const float* __restrict__ B,
             float* __restrict__ C,
             const float* __restrict__ bias,
             int K, int lda, int ldb, int ldc,
             long long strideAb, long long strideBb, long long strideCb)
{
    constexpr int STAGE_B = HYBRID ? STAGE_HYB : STAGE_BF2;
    extern __shared__ char sm[];

    const int tid  = threadIdx.x;
    const int lane = tid & 31;
    const int w    = tid >> 5;
    const int q    = lane >> 2;
    const int r    = lane & 3;
    const int wm   = (w & 1) * 64;
    const int wn   = (w >> 1) * 32;

    A += (long long)blockIdx.z * strideAb;
    B += (long long)blockIdx.z * strideBb;
    C += (long long)blockIdx.z * strideCb;
    const int bm = blockIdx.y * 128;
    const int bn = blockIdx.x * 128;

    float4 stA[4], stB[4];

    auto ldg = [&](int k0) {
#pragma unroll
        for (int i = 0; i < 4; i++) {
            int c = tid + 256 * i;
            int row = c >> 3, kb = (c & 7) << 2;
            stA[i] = *(const float4*)&A[(long long)(bm + row) * lda + k0 + kb];
            stB[i] = *(const float4*)&B[(long long)(bn + row) * ldb + k0 + kb];
        }
    };

    auto sts = [&](int st) {
        char* base = sm + st * STAGE_B;
        float* AhF = (float*)base;
        float* BhF = (float*)(base + TFT_B);
        uint32_t* AHB = (uint32_t*)(base + (HYBRID ? 2 * TFT_B : 0));
        uint32_t* ALB = AHB + 2560;
        uint32_t* BHB = ALB + 2560;
        uint32_t* BLB = BHB + 2560;
#pragma unroll
        for (int i = 0; i < 4; i++) {
            int c = tid + 256 * i;
            int row = c >> 3, kb = (c & 7) << 2;
            int bfo = row * 20 + (kb >> 1);
            {
                float4 v = stA[i];
                if (HYBRID) {
                    float4 h, l;
                    h.x = f2tf32(v.x); l.x = v.x - h.x;
                    h.y = f2tf32(v.y); l.y = v.y - h.y;
                    h.z = f2tf32(v.z); l.z = v.z - h.z;
                    h.w = f2tf32(v.w); l.w = v.w - h.w;
                    *(float4*)&AhF[row * 36 + kb] = h;
                    *(uint2*)&AHB[bfo] = make_uint2(pack_bf16(h.x, h.y), pack_bf16(h.z, h.w));
                    *(uint2*)&ALB[bfo] = make_uint2(pack_bf16(l.x, l.y), pack_bf16(l.z, l.w));
                } else {
                    uint32_t h0 = pack_bf16(v.x, v.y), h1 = pack_bf16(v.z, v.w);
                    float h0lo, h0hi, h1lo, h1hi;
                    unpack_bf16(h0, h0lo, h0hi);
                    unpack_bf16(h1, h1lo, h1hi);
                    *(uint2*)&AHB[bfo] = make_uint2(h0, h1);
                    *(uint2*)&ALB[bfo] = make_uint2(pack_bf16(v.x - h0lo, v.y - h0hi),
                                                    pack_bf16(v.z - h1lo, v.w - h1hi));
                }
            }
            {
                float4 v = stB[i];
                if (HYBRID) {
                    float4 h, l;
                    h.x = f2tf32(v.x); l.x = v.x - h.x;
                    h.y = f2tf32(v.y); l.y = v.y - h.y;
                    h.z = f2tf32(v.z); l.z = v.z - h.z;
                    h.w = f2tf32(v.w); l.w = v.w - h.w;
                    *(float4*)&BhF[row * 36 + kb] = h;
                    *(uint2*)&BHB[bfo] = make_uint2(pack_bf16(h.x, h.y), pack_bf16(h.z, h.w));
                    *(uint2*)&BLB[bfo] = make_uint2(pack_bf16(l.x, l.y), pack_bf16(l.z, l.w));
                } else {
                    uint32_t h0 = pack_bf16(v.x, v.y), h1 = pack_bf16(v.z, v.w);
                    float h0lo, h0hi, h1lo, h1hi;
                    unpack_bf16(h0, h0lo, h0hi);
                    unpack_bf16(h1, h1lo, h1hi);
                    *(uint2*)&BHB[bfo] = make_uint2(h0, h1);
                    *(uint2*)&BLB[bfo] = make_uint2(pack_bf16(v.x - h0lo, v.y - h0hi),
                                                    pack_bf16(v.z - h1lo, v.w - h1hi));
                }
            }
        }
    };

    float acc[4][4][4] = {};

    auto compute = [&](int st) {
        char* base = sm + st * STAGE_B;
        const uint32_t* AhF = (const uint32_t*)base;
        const uint32_t* BhF = (const uint32_t*)(base + TFT_B);
        const uint32_t* AHB = (const uint32_t*)(base + (HYBRID ? 2 * TFT_B : 0));
        const uint32_t* ALB = AHB + 2560;
        const uint32_t* BHB = ALB + 2560;
        const uint32_t* BLB = BHB + 2560;
#pragma unroll
        for (int k16 = 0; k16 < 2; k16++) {
            const int c0 = k16 * 8;          // bf16 word-column offset
            // ---- bf16 fragments (k16 wide) ----
            uint32_t ahb[4][4], alb[4][4], bhb[4][2], blb[4][2];
#pragma unroll
            for (int mi = 0; mi < 4; mi++) {
                int m0 = wm + mi * 16 + q;
                ahb[mi][0] = AHB[(m0)     * 20 + c0 + r];
                ahb[mi][1] = AHB[(m0 + 8) * 20 + c0 + r];
                ahb[mi][2] = AHB[(m0)     * 20 + c0 + r + 4];
                ahb[mi][3] = AHB[(m0 + 8) * 20 + c0 + r + 4];
                alb[mi][0] = ALB[(m0)     * 20 + c0 + r];
                alb[mi][1] = ALB[(m0 + 8) * 20 + c0 + r];
                alb[mi][2] = ALB[(m0)     * 20 + c0 + r + 4];
                alb[mi][3] = ALB[(m0 + 8) * 20 + c0 + r + 4];
            }
#pragma unroll
            for (int ni = 0; ni < 4; ni++) {
                int n0 = wn + ni * 8 + q;
                bhb[ni][0] = BHB[n0 * 20 + c0 + r];
                bhb[ni][1] = BHB[n0 * 20 + c0 + r + 4];
                blb[ni][0] = BLB[n0 * 20 + c0 + r];
                blb[ni][1] = BLB[n0 * 20 + c0 + r + 4];
            }
            // cross terms (and for bf16x2 also hi*hi)
#pragma unroll
            for (int mi = 0; mi < 4; mi++)
#pragma unroll
                for (int ni = 0; ni < 4; ni++)
                    mma_bf16(acc[mi][ni], ahb[mi], blb[ni]);
#pragma unroll
            for (int mi = 0; mi < 4; mi++)
#pragma unroll
                for (int ni = 0; ni < 4; ni++)
                    mma_bf16(acc[mi][ni], alb[mi], bhb[ni]);
            if (!HYBRID) {
#pragma unroll
                for (int mi = 0; mi < 4; mi++)
#pragma unroll
                    for (int ni = 0; ni < 4; ni++)
                        mma_bf16(acc[mi][ni], ahb[mi], bhb[ni]);
            } else {
                // ---- tf32 hi*hi, two k8 chunks ----
#pragma unroll
                for (int kc = 0; kc < 2; kc++) {
                    const int kk = k16 * 16 + kc * 8;
                    uint32_t ah[4][4], bh[4][2];
#pragma unroll
                    for (int mi = 0; mi < 4; mi++) {
                        int m0 = wm + mi * 16 + q;
                        ah[mi][0] = AhF[(m0)     * 36 + kk + r];
                        ah[mi][1] = AhF[(m0 + 8) * 36 + kk + r];
                        ah[mi][2] = AhF[(m0)     * 36 + kk + r + 4];
                        ah[mi][3] = AhF[(m0 + 8) * 36 + kk + r + 4];
                    }
#pragma unroll
                    for (int ni = 0; ni < 4; ni++) {
                        int n0 = wn + ni * 8 + q;
                        bh[ni][0] = BhF[n0 * 36 + kk + r];
                        bh[ni][1] = BhF[n0 * 36 + kk + r + 4];
                    }
#pragma unroll
                    for (int mi = 0; mi < 4; mi++)
#pragma unroll
                        for (int ni = 0; ni < 4; ni++)
                            mma_tf32(acc[mi][ni], ah[mi], bh[ni]);
                }
            }
        }
    };

    const int iters = K >> 5;

    ldg(0);
    sts(0);
    if (iters > 1) ldg(32);
    __syncthreads();

    for (int it = 0; it < iters; ++it) {
        compute(it & 1);
        if (it + 1 < iters) {
            sts((it + 1) & 1);
            if (it + 2 < iters) ldg((it + 2) << 5);
        }
        __syncthreads();
    }

    // ---- epilogue ----------------------------------------------------------
#pragma unroll
    for (int mi = 0; mi < 4; mi++) {
#pragma unroll
        for (int ni = 0; ni < 4; ni++) {
            int row = bm + wm + mi * 16 + q;
            int col = bn + wn + ni * 8 + 2 * r;
            float2 v0 = make_float2(acc[mi][ni][0], acc[mi][ni][1]);
            float2 v1 = make_float2(acc[mi][ni][2], acc[mi][ni][3]);
            if (bias) {
                float2 bb = *(const float2*)&bias[col];
                v0.x += bb.x; v0.y += bb.y;
                v1.x += bb.x; v1.y += bb.y;
            }
            *(float2*)&C[(long long)row * ldc + col]       = v0;
            *(float2*)&C[(long long)(row + 8) * ldc + col] = v1;
        }
    }
}

// ---------------------------------------------------------------------------
// Softmax over rows of length SQ (in place). One block per row.
// ---------------------------------------------------------------------------
__global__ void softmax_kernel(float* __restrict__ logits)
{
    float* row = logits + (long long)blockIdx.x * SQ;
    __shared__ float red[256];
    int t = threadIdx.x;

    float m = -3.4e38f;
    for (int i = t; i < SQ; i += 256) m = fmaxf(m, row[i]);
    red[t] = m;
    __syncthreads();
    for (int s = 128; s > 0; s >>= 1) {
        if (t < s) red[t] = fmaxf(red[t], red[t + s]);
        __syncthreads();
    }
    m = red[0];
    __syncthreads();

    float sum = 0.0f;
    for (int i = t; i < SQ; i += 256) {
        float e = __expf(row[i] - m);
        row[i] = e;
        sum += e;
    }
    red[t] = sum;
    __syncthreads();
    for (int s = 128; s > 0; s >>= 1) {
        if (t < s) red[t] += red[t + s];
        __syncthreads();
    }
    float inv = 1.0f / red[0];
    for (int i = t; i < SQ; i += 256) row[i] *= inv;
}

// ---------------------------------------------------------------------------
// Launch
// ---------------------------------------------------------------------------
extern "C" void kernel_launch(void* const* d_in, const int* in_sizes, int n_in,
                              void* d_out, int out_size)
{
    const float* x         = (const float*)d_in[0];
    const float* relations = (const float*)d_in[1];
    const float* re_w1     = (const float*)d_in[2];
    const float* re_b1     = (const float*)d_in[3];
    const float* re_w2     = (const float*)d_in[4];
    const float* re_b2     = (const float*)d_in[5];
    const float* attn_w    = (const float*)d_in[6];
    const float* out_w     = (const float*)d_in[7];
    const float* out_b     = (const float*)d_in[8];
    float* out = (float*)d_out;

    float *hidden, *rel, *scores, *logits, *context, *rew2T, *attnwT, *outwT, *xT;
    cudaGetSymbolAddress((void**)&hidden,  g_hidden);
    cudaGetSymbolAddress((void**)&rel,     g_rel);
    cudaGetSymbolAddress((void**)&scores,  g_scores);
    cudaGetSymbolAddress((void**)&logits,  g_logits);
    cudaGetSymbolAddress((void**)&context, g_context);
    cudaGetSymbolAddress((void**)&rew2T,   g_rew2T);
    cudaGetSymbolAddress((void**)&attnwT,  g_attnwT);
    cudaGetSymbolAddress((void**)&outwT,   g_outwT);
    cudaGetSymbolAddress((void**)&xT,      g_xT);

    const int smemH = 2 * STAGE_HYB;   // 155648
    const int smemB = 2 * STAGE_BF2;   // 81920
    cudaFuncSetAttribute(gemm_nt<1>, cudaFuncAttributeMaxDynamicSharedMemorySize, smemH);
    cudaFuncSetAttribute(gemm_nt<0>, cudaFuncAttributeMaxDynamicSharedMemorySize, smemB);

    // 0) transposes so every GEMM is NT (B stored [N,K] K-major)
    transpose_kernel<<<dim3(32, 32, 1), dim3(32, 8)>>>(re_w2, rew2T, DM, DM, 0, 0);
    transpose_kernel<<<dim3(32, 32, NH), dim3(32, 8)>>>(attn_w, attnwT, DM, DM,
                                                        (long long)DM * DM, (long long)DM * DM);
    transpose_kernel<<<dim3(32, 256, 1), dim3(32, 8)>>>(out_w, outwT, NH * DM, DM, 0, 0);
    transpose_kernel<<<dim3(32, 64, 1), dim3(32, 8)>>>(x, xT, SQ, DM, 0, 0);

    // 1) hidden = relu(relations @ re_w1 + b1)
    rel_hidden_kernel<<<(SQ * DM) / 256, 256>>>(relations, re_w1, re_b1, hidden);

    // 2) rel = hidden @ re_w2 + b2                      (hybrid precision)
    gemm_nt<1><<<dim3(DM / 128, SQ / 128, 1), 256, smemH>>>(
        hidden, rew2T, rel, re_b2, DM, DM, DM, DM, 0, 0, 0);

    // 3) scores[h] = x @ attn_w[h]                      (hybrid)
    gemm_nt<1><<<dim3(DM / 128, SQ / 128, NH), 256, smemH>>>(
        x, attnwT, scores, nullptr, DM, DM, DM, DM,
        0, (long long)DM * DM, (long long)SQ * DM);

    // 4) logits[h] = rel @ K_h^T ; key row t = scores[(t*NH + h)*DM ...]  (hybrid)
    gemm_nt<1><<<dim3(SQ / 128, SQ / 128, NH), 256, smemH>>>(
        rel, scores, logits, nullptr, DM, DM, NH * DM, SQ,
        0, (long long)DM, (long long)SQ * SQ);

    // 5) softmax rows (in place)
    softmax_kernel<<<NH * SQ, 256>>>(logits);

    // 6) context = attn @ x      (bf16x2, post-softmax)
    gemm_nt<0><<<dim3(DM / 128, SQ / 128, NH), 256, smemB>>>(
        logits, xT, context, nullptr, SQ, SQ, SQ, NH * DM,
        (long long)SQ * SQ, 0, (long long)DM);

    // 7) out = context @ out_w + out_b   (bf16x2)
    gemm_nt<0><<<dim3(DM / 128, SQ / 128, 1), 256, smemB>>>(
        context, outwT, out, out_b, NH * DM, NH * DM, NH * DM, DM, 0, 0, 0);

    (void)in_sizes; (void)n_in; (void)out_size;
}

// round 11
// speedup vs baseline: 2.3491x; 1.0869x over previous
#include <cuda_runtime.h>
#include <cuda_fp16.h>
#include <cstdint>

#define SQ 2048
#define DM 1024
#define NH 8

// ---------------------------------------------------------------------------
// Scratch (device globals; no allocation allowed)
// ---------------------------------------------------------------------------
__device__ float g_hidden[(long)SQ * DM];            // 8 MB
__device__ float g_rel[(long)SQ * DM];               // 8 MB
__device__ float g_scores[(long)NH * SQ * DM];       // 64 MB  raw [H,S,D]
__device__ float g_logits[(long)NH * SQ * SQ];       // 128 MB [H,S,S]
__device__ float g_context[(long)SQ * NH * DM];      // 64 MB  [S, H*D]
__device__ float g_rew2T[(long)DM * DM];             // 4 MB   re_w2^T   [N,K]
__device__ float g_attnwT[(long)NH * DM * DM];       // 32 MB  attn_w^T per head
__device__ float g_outwT[(long)DM * NH * DM];        // 32 MB  out_w^T   [1024, 8192]
__device__ float g_xT[(long)DM * SQ];                // 8 MB   x^T       [1024, 2048]

// ---------------------------------------------------------------------------
// helpers
// ---------------------------------------------------------------------------
// pack two floats as f16x2 word {lo in [15:0], hi in [31:16]}
__device__ __forceinline__ uint32_t pack_f16(float lo, float hi) {
    uint32_t w;
    asm("cvt.rn.f16x2.f32 %0, %1, %2;" : "=r"(w) : "f"(hi), "f"(lo));
    return w;
}
// unpack f16x2 word back to the exact fp32 values it represents
__device__ __forceinline__ void unpack_f16(uint32_t w, float& lo, float& hi) {
    __half2 h = *(__half2*)&w;
    lo = __low2float(h);
    hi = __high2float(h);
}

__device__ __forceinline__ void mma_f16(float c[4], const uint32_t a[4], const uint32_t b[2]) {
    asm volatile(
        "mma.sync.aligned.m16n8k16.row.col.f32.f16.f16.f32 "
        "{%0,%1,%2,%3}, {%4,%5,%6,%7}, {%8,%9}, {%0,%1,%2,%3};\n"
        : "+f"(c[0]), "+f"(c[1]), "+f"(c[2]), "+f"(c[3])
        : "r"(a[0]), "r"(a[1]), "r"(a[2]), "r"(a[3]), "r"(b[0]), "r"(b[1]));
}

// ---------------------------------------------------------------------------
// hidden = relu(relations @ re_w1 + b1)
// ---------------------------------------------------------------------------
__global__ void rel_hidden_kernel(const float* __restrict__ relations,
                                  const float* __restrict__ w1,
                                  const float* __restrict__ b1,
                                  float* __restrict__ hidden)
{
    int idx = blockIdx.x * blockDim.x + threadIdx.x;
    int s = idx >> 10;
    int d = idx & (DM - 1);
    float v = b1[d];
    v = fmaf(relations[s * 4 + 0], w1[0 * DM + d], v);
    v = fmaf(relations[s * 4 + 1], w1[1 * DM + d], v);
    v = fmaf(relations[s * 4 + 2], w1[2 * DM + d], v);
    v = fmaf(relations[s * 4 + 3], w1[3 * DM + d], v);
    hidden[idx] = fmaxf(v, 0.0f);
}

// ---------------------------------------------------------------------------
// Transpose: out[b][c][r] = in[b][r][c]. R, C multiples of 32. block (32,8).
// ---------------------------------------------------------------------------
__global__ void transpose_kernel(const float* __restrict__ in, float* __restrict__ out,
                                 int R, int C, long long strideIn, long long strideOut)
{
    __shared__ float t[32][33];
    in  += (long long)blockIdx.z * strideIn;
    out += (long long)blockIdx.z * strideOut;
    int r0 = blockIdx.y * 32, c0 = blockIdx.x * 32;
    int tx = threadIdx.x, ty = threadIdx.y;
#pragma unroll
    for (int i = 0; i < 4; i++)
        t[ty + 8 * i][tx] = in[(long long)(r0 + ty + 8 * i) * C + c0 + tx];
    __syncthreads();
#pragma unroll
    for (int i = 0; i < 4; i++)
        out[(long long)(c0 + ty + 8 * i) * R + r0 + tx] = t[tx][ty + 8 * i];
}

// ---------------------------------------------------------------------------
// fp16x2 3-term NT GEMM (error-compensated, ~1e-6 accuracy class).
//   C[M,N] = A[M,K] @ B[N,K]^T (+bias)
// CTA tile 128x128, BK=32, 256 threads, warp tile 64x32 (4x4 of m16n8k16).
// Per k16: 3 fp16 MMAs: Ah*Bl, Al*Bh, Ah*Bh  (al = fp16(a - fp16(a)))
// smem per stage: AH, AL, BH, BL f16x2 tiles [128 rows][20 u32 words].
// Double-buffered; 2 CTAs/SM (80KB smem, <=128 regs).
// ---------------------------------------------------------------------------
#define FT_W 2560              // words per tile (128*20)
#define STAGE_B (4 * FT_W * 4) // 40960 bytes

__global__ __launch_bounds__(256, 2)
void gemm_f16x2(const float* __restrict__ A,
                const float* __restrict__ B,
                float* __restrict__ C,
                const float* __restrict__ bias,
                int K, int lda, int ldb, int ldc,
                long long strideAb, long long strideBb, long long strideCb)
{
    extern __shared__ char sm[];

    const int tid  = threadIdx.x;
    const int lane = tid & 31;
    const int w    = tid >> 5;
    const int q    = lane >> 2;
    const int r    = lane & 3;
    const int wm   = (w & 1) * 64;
    const int wn   = (w >> 1) * 32;

    A += (long long)blockIdx.z * strideAb;
    B += (long long)blockIdx.z * strideBb;
    C += (long long)blockIdx.z * strideCb;
    const int bm = blockIdx.y * 128;
    const int bn = blockIdx.x * 128;

    float4 stA[4], stB[4];

    auto ldg = [&](int k0) {
#pragma unroll
        for (int i = 0; i < 4; i++) {
            int c = tid + 256 * i;
            int row = c >> 3, kb = (c & 7) << 2;
            stA[i] = *(const float4*)&A[(long long)(bm + row) * lda + k0 + kb];
            stB[i] = *(const float4*)&B[(long long)(bn + row) * ldb + k0 + kb];
        }
    };

    auto sts = [&](int st) {
        uint32_t* AH = (uint32_t*)(sm + st * STAGE_B);
        uint32_t* AL = AH + FT_W;
        uint32_t* BH = AL + FT_W;
        uint32_t* BL = BH + FT_W;
#pragma unroll
        for (int i = 0; i < 4; i++) {
            int c = tid + 256 * i;
            int row = c >> 3, kb = (c & 7) << 2;
            int o = row * 20 + (kb >> 1);
            {
                float4 v = stA[i];
                uint32_t h0 = pack_f16(v.x, v.y), h1 = pack_f16(v.z, v.w);
                float a0, a1, a2, a3;
                unpack_f16(h0, a0, a1);
                unpack_f16(h1, a2, a3);
                *(uint2*)&AH[o] = make_uint2(h0, h1);
                *(uint2*)&AL[o] = make_uint2(pack_f16(v.x - a0, v.y - a1),
                                             pack_f16(v.z - a2, v.w - a3));
            }
            {
                float4 v = stB[i];
                uint32_t h0 = pack_f16(v.x, v.y), h1 = pack_f16(v.z, v.w);
                float b0, b1, b2, b3;
                unpack_f16(h0, b0, b1);
                unpack_f16(h1, b2, b3);
                *(uint2*)&BH[o] = make_uint2(h0, h1);
                *(uint2*)&BL[o] = make_uint2(pack_f16(v.x - b0, v.y - b1),
                                             pack_f16(v.z - b2, v.w - b3));
            }
        }
    };

    float acc[4][4][4] = {};

    auto compute = [&](int st) {
        const uint32_t* AH = (const uint32_t*)(sm + st * STAGE_B);
        const uint32_t* AL = AH + FT_W;
        const uint32_t* BH = AL + FT_W;
        const uint32_t* BL = BH + FT_W;
#pragma unroll
        for (int k16 = 0; k16 < 2; k16++) {
            const int c0 = k16 * 8;
            uint32_t ah[4][4], al[4][4], bh[4][2], bl[4][2];
#pragma unroll
            for (int mi = 0; mi < 4; mi++) {
                int m0 = wm + mi * 16 + q;
                ah[mi][0] = AH[(m0)     * 20 + c0 + r];
                ah[mi][1] = AH[(m0 + 8) * 20 + c0 + r];
                ah[mi][2] = AH[(m0)     * 20 + c0 + r + 4];
                ah[mi][3] = AH[(m0 + 8) * 20 + c0 + r + 4];
                al[mi][0] = AL[(m0)     * 20 + c0 + r];
                al[mi][1] = AL[(m0 + 8) * 20 + c0 + r];
                al[mi][2] = AL[(m0)     * 20 + c0 + r + 4];
                al[mi][3] = AL[(m0 + 8) * 20 + c0 + r + 4];
            }
#pragma unroll
            for (int ni = 0; ni < 4; ni++) {
                int n0 = wn + ni * 8 + q;
                bh[ni][0] = BH[n0 * 20 + c0 + r];
                bh[ni][1] = BH[n0 * 20 + c0 + r + 4];
                bl[ni][0] = BL[n0 * 20 + c0 + r];
                bl[ni][1] = BL[n0 * 20 + c0 + r + 4];
            }
            // term-major: 16 independent accumulators between reuses
#pragma unroll
            for (int mi = 0; mi < 4; mi++)
#pragma unroll
                for (int ni = 0; ni < 4; ni++)
                    mma_f16(acc[mi][ni], ah[mi], bl[ni]);
#pragma unroll
            for (int mi = 0; mi < 4; mi++)
#pragma unroll
                for (int ni = 0; ni < 4; ni++)
                    mma_f16(acc[mi][ni], al[mi], bh[ni]);
#pragma unroll
            for (int mi = 0; mi < 4; mi++)
#pragma unroll
                for (int ni = 0; ni < 4; ni++)
                    mma_f16(acc[mi][ni], ah[mi], bh[ni]);
        }
    };

    const int iters = K >> 5;

    ldg(0);
    sts(0);
    if (iters > 1) ldg(32);
    __syncthreads();

    for (int it = 0; it < iters; ++it) {
        compute(it & 1);
        if (it + 1 < iters) {
            sts((it + 1) & 1);
            if (it + 2 < iters) ldg((it + 2) << 5);
        }
        __syncthreads();
    }

    // ---- epilogue ----------------------------------------------------------
#pragma unroll
    for (int mi = 0; mi < 4; mi++) {
#pragma unroll
        for (int ni = 0; ni < 4; ni++) {
            int row = bm + wm + mi * 16 + q;
            int col = bn + wn + ni * 8 + 2 * r;
            float2 v0 = make_float2(acc[mi][ni][0], acc[mi][ni][1]);
            float2 v1 = make_float2(acc[mi][ni][2], acc[mi][ni][3]);
            if (bias) {
                float2 bb = *(const float2*)&bias[col];
                v0.x += bb.x; v0.y += bb.y;
                v1.x += bb.x; v1.y += bb.y;
            }
            *(float2*)&C[(long long)row * ldc + col]       = v0;
            *(float2*)&C[(long long)(row + 8) * ldc + col] = v1;
        }
    }
}

// ---------------------------------------------------------------------------
// Softmax over rows of length SQ (in place). One block (256 thr) per row;
// 8 values per thread held in registers: 1 gmem read + 1 write total.
// ---------------------------------------------------------------------------
__global__ __launch_bounds__(256)
void softmax_kernel(float* __restrict__ logits)
{
    float* row = logits + (long long)blockIdx.x * SQ;
    const int t = threadIdx.x;
    const int lane = t & 31, w = t >> 5;
    __shared__ float redm[8], reds[8];

    float4 a = *(float4*)&row[t * 8];
    float4 b = *(float4*)&row[t * 8 + 4];

    float m = fmaxf(fmaxf(fmaxf(a.x, a.y), fmaxf(a.z, a.w)),
                    fmaxf(fmaxf(b.x, b.y), fmaxf(b.z, b.w)));
#pragma unroll
    for (int o = 16; o > 0; o >>= 1) m = fmaxf(m, __shfl_xor_sync(0xffffffffu, m, o));
    if (lane == 0) redm[w] = m;
    __syncthreads();
    float mm = redm[0];
#pragma unroll
    for (int i = 1; i < 8; i++) mm = fmaxf(mm, redm[i]);

    a.x = __expf(a.x - mm); a.y = __expf(a.y - mm);
    a.z = __expf(a.z - mm); a.w = __expf(a.w - mm);
    b.x = __expf(b.x - mm); b.y = __expf(b.y - mm);
    b.z = __expf(b.z - mm); b.w = __expf(b.w - mm);

    float s = (a.x + a.y) + (a.z + a.w) + (b.x + b.y) + (b.z + b.w);
#pragma unroll
    for (int o = 16; o > 0; o >>= 1) s += __shfl_xor_sync(0xffffffffu, s, o);
    if (lane == 0) reds[w] = s;
    __syncthreads();
    float ss = reds[0];
#pragma unroll
    for (int i = 1; i < 8; i++) ss += reds[i];
    float inv = 1.0f / ss;

    a.x *= inv; a.y *= inv; a.z *= inv; a.w *= inv;
    b.x *= inv; b.y *= inv; b.z *= inv; b.w *= inv;
    *(float4*)&row[t * 8]     = a;
    *(float4*)&row[t * 8 + 4] = b;
}

// ---------------------------------------------------------------------------
// Launch
// ---------------------------------------------------------------------------
extern "C" void kernel_launch(void* const* d_in, const int* in_sizes, int n_in,
                              void* d_out, int out_size)
{
    const float* x         = (const float*)d_in[0];
    const float* relations = (const float*)d_in[1];
    const float* re_w1     = (const float*)d_in[2];
    const float* re_b1     = (const float*)d_in[3];
    const float* re_w2     = (const float*)d_in[4];
    const float* re_b2     = (const float*)d_in[5];
    const float* attn_w    = (const float*)d_in[6];
    const float* out_w     = (const float*)d_in[7];
    const float* out_b     = (const float*)d_in[8];
    float* out = (float*)d_out;

    float *hidden, *rel, *scores, *logits, *context, *rew2T, *attnwT, *outwT, *xT;
    cudaGetSymbolAddress((void**)&hidden,  g_hidden);
    cudaGetSymbolAddress((void**)&rel,     g_rel);
    cudaGetSymbolAddress((void**)&scores,  g_scores);
    cudaGetSymbolAddress((void**)&logits,  g_logits);
    cudaGetSymbolAddress((void**)&context, g_context);
    cudaGetSymbolAddress((void**)&rew2T,   g_rew2T);
    cudaGetSymbolAddress((void**)&attnwT,  g_attnwT);
    cudaGetSymbolAddress((void**)&outwT,   g_outwT);
    cudaGetSymbolAddress((void**)&xT,      g_xT);

    const int smemB = 2 * STAGE_B;   // 81920
    cudaFuncSetAttribute(gemm_f16x2, cudaFuncAttributeMaxDynamicSharedMemorySize, smemB);

    // 0) transposes so every GEMM is NT (B stored [N,K] K-major)
    transpose_kernel<<<dim3(32, 32, 1), dim3(32, 8)>>>(re_w2, rew2T, DM, DM, 0, 0);
    transpose_kernel<<<dim3(32, 32, NH), dim3(32, 8)>>>(attn_w, attnwT, DM, DM,
                                                        (long long)DM * DM, (long long)DM * DM);
    transpose_kernel<<<dim3(32, 256, 1), dim3(32, 8)>>>(out_w, outwT, NH * DM, DM, 0, 0);
    transpose_kernel<<<dim3(32, 64, 1), dim3(32, 8)>>>(x, xT, SQ, DM, 0, 0);

    // 1) hidden = relu(relations @ re_w1 + b1)
    rel_hidden_kernel<<<(SQ * DM) / 256, 256>>>(relations, re_w1, re_b1, hidden);

    // 2) rel = hidden @ re_w2 + b2
    gemm_f16x2<<<dim3(DM / 128, SQ / 128, 1), 256, smemB>>>(
        hidden, rew2T, rel, re_b2, DM, DM, DM, DM, 0, 0, 0);

    // 3) scores[h] = x @ attn_w[h]
    gemm_f16x2<<<dim3(DM / 128, SQ / 128, NH), 256, smemB>>>(
        x, attnwT, scores, nullptr, DM, DM, DM, DM,
        0, (long long)DM * DM, (long long)SQ * DM);

    // 4) logits[h] = rel @ K_h^T ; key row t = scores[(t*NH + h)*DM ...] (K-major)
    gemm_f16x2<<<dim3(SQ / 128, SQ / 128, NH), 256, smemB>>>(
        rel, scores, logits, nullptr, DM, DM, NH * DM, SQ,
        0, (long long)DM, (long long)SQ * SQ);

    // 5) softmax rows (in place, register-resident)
    softmax_kernel<<<NH * SQ, 256>>>(logits);

    // 6) context = attn @ x      (B = x^T)
    gemm_f16x2<<<dim3(DM / 128, SQ / 128, NH), 256, smemB>>>(
        logits, xT, context, nullptr, SQ, SQ, SQ, NH * DM,
        (long long)SQ * SQ, 0, (long long)DM);

    // 7) out = context @ out_w + out_b   (B = out_w^T)
    gemm_f16x2<<<dim3(DM / 128, SQ / 128, 1), 256, smemB>>>(
        context, outwT, out, out_b, NH * DM, NH * DM, NH * DM, DM, 0, 0, 0);

    (void)in_sizes; (void)n_in; (void)out_size;
}